// round 5
// baseline (speedup 1.0000x reference)
#include <cuda_runtime.h>
#include <cstdint>

// Problem constants (fixed by reference)
#define NB   8
#define HH   512
#define WW   512
#define DD   8
#define HWC  (HH * WW)          // 262144
#define NPIX (NB * HWC)         // 2097152 = 2^21
#define TPB  256
#define NBLK (NPIX / TPB)       // 8192

// smem attr row stride in words: 24 payload + 4 pad = 28 (112 B, 16B-aligned).
// STS.128/LDS.128 legal at offsets 0,8,16 (+4) within a row.
#define ASTRIDE 28

// 256-bit gather load with L2 evict_last (sm_103 requires v8.b32 for this hint).
// Loads 32 B: two float4s.
__device__ __forceinline__ void ldg256_el(const void* p, float4& a, float4& b) {
    asm volatile(
        "ld.global.nc.L2::evict_last.v8.b32 {%0,%1,%2,%3,%4,%5,%6,%7}, [%8];"
        : "=r"(*(unsigned*)&a.x), "=r"(*(unsigned*)&a.y),
          "=r"(*(unsigned*)&a.z), "=r"(*(unsigned*)&a.w),
          "=r"(*(unsigned*)&b.x), "=r"(*(unsigned*)&b.y),
          "=r"(*(unsigned*)&b.z), "=r"(*(unsigned*)&b.w)
        : "l"(p));
}

__global__ __launch_bounds__(TPB, 4)
void interp_kernel(const void* __restrict__ p2f_raw,
                   const float* __restrict__ bary,     // [NPIX,3]
                   const float* __restrict__ attr,     // [N*NF][3][8] fp32 = 96 B/face
                   float* __restrict__ out)            // [N][9][H][W]
{
    __shared__ float s_attr[TPB * ASTRIDE];  // 28.7 KB

    const int tid   = threadIdx.x;
    const int pix   = blockIdx.x * TPB + tid;
    const int lane  = tid & 31;
    const int wbase = tid & ~31;             // warp's first slot in block

    // ---- dtype detection (int64 vs int32 pix_to_face), warp-uniform ----
    // High-word positions with j < NPIX/2 are in-bounds under BOTH interpretations.
    // int64: hi word is 0 or 0xFFFFFFFF for every element -> 32/32 match.
    // int32: sampled words are arbitrary face values -> ~6-7/32 match.
    const unsigned int* pw = (const unsigned int*)p2f_raw;
    unsigned int hi = __ldg(&pw[2 * (pix & (NPIX / 2 - 1)) + 1]);
    bool m = (hi == 0u) || (hi == 0xFFFFFFFFu);
    bool is64 = __popc(__ballot_sync(0xffffffffu, m)) >= 28;

    // ---- own pixel: face index + barycentrics (single-use -> evict-first) ----
    int f;
    if (is64) f = (int)__ldcs((const long long*)p2f_raw + pix);  // faces < 8e5 fit int32
    else      f = __ldcs((const int*)p2f_raw + pix);

    const float* bp = bary + (size_t)pix * 3;
    float b0 = __ldcs(bp + 0);
    float b1 = __ldcs(bp + 1);
    float b2 = __ldcs(bp + 2);

    // ---- warp-cooperative gather: 32 faces x 96B = 96 x 32B = 3 full iters ----
    // iter i, lane l covers packed index p = i*32 + l: slot q = p/3, sub = p%3.
    int q   = lane / 3;                      // note: lanes 30,31 of i=0 map via p math below
    int sub = lane - q * 3;
    int faces[3], qs[3], subs[3];
    #pragma unroll
    for (int i = 0; i < 3; i++) {
        faces[i] = __shfl_sync(0xffffffffu, f, q);
        qs[i] = q; subs[i] = sub;
        sub += 2; q += 10;                   // advance p by 32 = 10*3 + 2
        if (sub >= 3) { sub -= 3; q += 1; }
    }
    float4 va[3], vb[3];
    #pragma unroll
    for (int i = 0; i < 3; i++) {
        if (faces[i] >= 0)
            ldg256_el(attr + (size_t)faces[i] * 24 + subs[i] * 8, va[i], vb[i]);
    }
    #pragma unroll
    for (int i = 0; i < 3; i++) {
        if (faces[i] >= 0) {
            float4* dst = (float4*)&s_attr[(wbase + qs[i]) * ASTRIDE + subs[i] * 8];
            dst[0] = va[i];                  // STS.128
            dst[1] = vb[i];                  // STS.128
        }
    }
    __syncwarp();   // producer == consumer warp; no cross-warp coupling

    // ---- interpolate: o[d] = b0*A[v0,d] + b1*A[v1,d] + b2*A[v2,d] ----
    float o[DD];
    float vis;
    if (f >= 0) {
        const float4* a4 = (const float4*)&s_attr[tid * ASTRIDE];  // LDS.128 x6
        float4 A0 = a4[0], A1 = a4[1];   // vertex 0, ch 0-3 / 4-7
        float4 A2 = a4[2], A3 = a4[3];   // vertex 1
        float4 A4 = a4[4], A5 = a4[5];   // vertex 2
        o[0] = b0 * A0.x + b1 * A2.x + b2 * A4.x;
        o[1] = b0 * A0.y + b1 * A2.y + b2 * A4.y;
        o[2] = b0 * A0.z + b1 * A2.z + b2 * A4.z;
        o[3] = b0 * A0.w + b1 * A2.w + b2 * A4.w;
        o[4] = b0 * A1.x + b1 * A3.x + b2 * A5.x;
        o[5] = b0 * A1.y + b1 * A3.y + b2 * A5.y;
        o[6] = b0 * A1.z + b1 * A3.z + b2 * A5.z;
        o[7] = b0 * A1.w + b1 * A3.w + b2 * A5.w;
        vis = 1.0f;
    } else {
        #pragma unroll
        for (int d = 0; d < DD; d++) o[d] = 0.0f;
        vis = 0.0f;
    }

    // ---- output [N][9][H][W]: warp-coalesced plane-major stores, evict-first ----
    int n  = pix >> 18;            // / HWC (2^18)
    int hw = pix & (HWC - 1);
    float* ob = out + (size_t)n * (DD + 1) * HWC + hw;
    #pragma unroll
    for (int d = 0; d < DD; d++)
        __stcs(ob + (size_t)d * HWC, o[d]);
    __stcs(ob + (size_t)DD * HWC, vis);
}

extern "C" void kernel_launch(void* const* d_in, const int* in_sizes, int n_in,
                              void* d_out, int out_size) {
    const void*  p2f  = d_in[0];                    // [N,H,W,1] int32 or int64
    const float* bary = (const float*)d_in[1];      // [N,H,W,1,3] fp32
    const float* attr = (const float*)d_in[2];      // [N,NF,3,8] fp32
    float*       out  = (float*)d_out;              // [N,9,H,W] fp32

    interp_kernel<<<NBLK, TPB>>>(p2f, bary, attr, out);
}

// round 6
// speedup vs baseline: 1.0885x; 1.0885x over previous
#include <cuda_runtime.h>
#include <cstdint>

// Problem constants (fixed by reference)
#define NB    8
#define HH    512
#define WW    512
#define DD    8
#define HWC   (HH * WW)          // 262144
#define NPIX  (NB * HWC)         // 2097152 = 2^21
#define TPB   256
#define GRID  1024
#define TOTAL (GRID * TPB)       // 262144 threads
#define ITERS (NPIX / TOTAL)     // 8 pixels per thread, exact

// 256-bit gather load with L2 evict_last (sm_103 requires v8.b32 for this hint).
__device__ __forceinline__ void ldg256_el(const void* p, float4& a, float4& b) {
    asm volatile(
        "ld.global.nc.L2::evict_last.v8.b32 {%0,%1,%2,%3,%4,%5,%6,%7}, [%8];"
        : "=r"(*(unsigned*)&a.x), "=r"(*(unsigned*)&a.y),
          "=r"(*(unsigned*)&a.z), "=r"(*(unsigned*)&a.w),
          "=r"(*(unsigned*)&b.x), "=r"(*(unsigned*)&b.y),
          "=r"(*(unsigned*)&b.z), "=r"(*(unsigned*)&b.w)
        : "l"(p));
}

__global__ __launch_bounds__(TPB, 3)
void interp_kernel(const void* __restrict__ p2f_raw,
                   const float* __restrict__ bary,     // [NPIX,3]
                   const float* __restrict__ attr,     // [N*NF][3][8] fp32 = 96 B/face
                   float* __restrict__ out)            // [N][9][H][W]
{
    const int t = blockIdx.x * TPB + threadIdx.x;      // base pixel (t < NPIX/8)

    // ---- dtype detection (int64 vs int32 pix_to_face), warp-uniform ----
    // t < NPIX/2, so word index 2t+1 is in-bounds under BOTH interpretations.
    // int64: hi word of every element is 0 or 0xFFFFFFFF -> 32/32 lanes match.
    // int32: sampled words are arbitrary face values -> ~6-7/32 match.
    const unsigned int* pw = (const unsigned int*)p2f_raw;
    unsigned int hiw = __ldg(&pw[2 * t + 1]);
    bool m = (hiw == 0u) || (hiw == 0xFFFFFFFFu);
    const bool is64 = __popc(__ballot_sync(0xffffffffu, m)) >= 28;

    // Pipeline state: 3 idx/bary slots, 2 attr buffers.
    int    fq[3];
    float  bq[3][3];
    float4 A[2][6];

    // issue face index + barycentrics for stage j into slot s (single-use -> evict-first)
    auto load_idx = [&](int s, int j) {
        int pix = t + j * TOTAL;
        if (is64) fq[s] = (int)__ldcs((const long long*)p2f_raw + pix);
        else      fq[s] = __ldcs((const int*)p2f_raw + pix);
        const float* bp = bary + (size_t)pix * 3;
        bq[s][0] = __ldcs(bp + 0);
        bq[s][1] = __ldcs(bp + 1);
        bq[s][2] = __ldcs(bp + 2);
    };

    // issue 3 x LDG.256 gather (96 B face payload) for slot s into buffer buf
    auto load_attr = [&](int buf, int s) {
        int f = fq[s];
        if (f >= 0) {
            const float* a = attr + (size_t)f * 24;
            ldg256_el(a + 0,  A[buf][0], A[buf][1]);   // vertex 0: ch 0-7
            ldg256_el(a + 8,  A[buf][2], A[buf][3]);   // vertex 1
            ldg256_el(a + 16, A[buf][4], A[buf][5]);   // vertex 2
        }
    };

    // ---- prologue: fill the pipe ----
    load_idx(0, 0);
    load_idx(1, 1);
    load_attr(0, 0);

    #pragma unroll
    for (int j = 0; j < ITERS; j++) {
        if (j + 2 < ITERS) load_idx((j + 2) % 3, j + 2);
        if (j + 1 < ITERS) load_attr((j + 1) & 1, (j + 1) % 3);

        // ---- compute + store stage j ----
        const int s   = j % 3;
        const int buf = j & 1;
        const int f   = fq[s];
        float o[DD], vis;
        if (f >= 0) {
            float b0 = bq[s][0], b1 = bq[s][1], b2 = bq[s][2];
            float4 A0 = A[buf][0], A1 = A[buf][1];
            float4 A2 = A[buf][2], A3 = A[buf][3];
            float4 A4 = A[buf][4], A5 = A[buf][5];
            o[0] = b0 * A0.x + b1 * A2.x + b2 * A4.x;
            o[1] = b0 * A0.y + b1 * A2.y + b2 * A4.y;
            o[2] = b0 * A0.z + b1 * A2.z + b2 * A4.z;
            o[3] = b0 * A0.w + b1 * A2.w + b2 * A4.w;
            o[4] = b0 * A1.x + b1 * A3.x + b2 * A5.x;
            o[5] = b0 * A1.y + b1 * A3.y + b2 * A5.y;
            o[6] = b0 * A1.z + b1 * A3.z + b2 * A5.z;
            o[7] = b0 * A1.w + b1 * A3.w + b2 * A5.w;
            vis = 1.0f;
        } else {
            #pragma unroll
            for (int d = 0; d < DD; d++) o[d] = 0.0f;
            vis = 0.0f;
        }

        // output [N][9][H][W]: warp-coalesced plane-major stores, evict-first
        int pix = t + j * TOTAL;
        int n   = pix >> 18;             // / HWC (2^18)
        int hw  = pix & (HWC - 1);
        float* ob = out + (size_t)n * (DD + 1) * HWC + hw;
        #pragma unroll
        for (int d = 0; d < DD; d++)
            __stcs(ob + (size_t)d * HWC, o[d]);
        __stcs(ob + (size_t)DD * HWC, vis);
    }
}

extern "C" void kernel_launch(void* const* d_in, const int* in_sizes, int n_in,
                              void* d_out, int out_size) {
    const void*  p2f  = d_in[0];                    // [N,H,W,1] int32 or int64
    const float* bary = (const float*)d_in[1];      // [N,H,W,1,3] fp32
    const float* attr = (const float*)d_in[2];      // [N,NF,3,8] fp32
    float*       out  = (float*)d_out;              // [N,9,H,W] fp32

    interp_kernel<<<GRID, TPB>>>(p2f, bary, attr, out);
}